// round 11
// baseline (speedup 1.0000x reference)
#include <cuda_runtime.h>
#include <cstdint>

#define NODES   64
#define NINPUT  16
#define NOUT    8
#define NEDGE   256
#define BATCH   8192
#define PASSES  64
#define G       16            // edge slots per chunk (lanes per column)
#define TB      128           // threads per block
#define CPB     8             // columns per block (2 cols per warp)
#define GRIDB   (BATCH / CPB) // 1024 blocks
#define STRIDE  65            // floats per column (64 nodes + scratch row 64)
#define MAXCH   522           // worst case (1 edge + 1 empty alternating) + pad

__device__ uint2 g_recs[MAXCH * G];
__device__ int   g_nchunks;   // total ring chunks incl. trailing dummy chunk

// 64-bit inclusive OR-scan across the warp
__device__ __forceinline__ unsigned long long orscan_incl(unsigned long long x,
                                                          int lane) {
    #pragma unroll
    for (int o = 1; o < 32; o <<= 1) {
        unsigned lo = __shfl_up_sync(0xffffffffu, (unsigned)x, o);
        unsigned hi = __shfl_up_sync(0xffffffffu, (unsigned)(x >> 32), o);
        unsigned long long y = ((unsigned long long)hi << 32) | lo;
        if (lane >= o) x |= y;
    }
    return x;
}

__device__ __forceinline__ unsigned long long bcast64(unsigned long long x,
                                                      int srclane) {
    unsigned lo = __shfl_sync(0xffffffffu, (unsigned)x, srclane);
    unsigned hi = __shfl_sync(0xffffffffu, (unsigned)(x >> 32), srclane);
    return ((unsigned long long)hi << 32) | lo;
}

// ---------------------------------------------------------------------------
// Warp-parallel greedy list scheduler (verified R6 base) + DISTANCE-2 rule:
// a candidate for chunk n must have src AND dst outside the member-write set
// of chunk n-1 (Wprev). This makes reads(c+1) disjoint from writes(c), which
// lets the main kernel issue chunk c+1's loads BEFORE chunk c's stores
// (software pipelining across the per-chunk latency chain).
// Other rules (proven in R6): RAW via W-footprint on src, WAR via R-footprint
// on dst, in-chunk dst distinctness; WAW across chunks relaxed (fp adds
// commute). Empty chunks clear Wprev -> no deadlock.
// A trailing all-dummy chunk per pass ring satisfies distance-2 at the pass
// boundary (dummies touch only scratch row 64; stale scratch reads harmless).
// rec.x = (dst_byte_off << 16) | src_byte_off, rec.y = w * 2*log2(e).
// ---------------------------------------------------------------------------
__global__ void sched_kernel(const float* __restrict__ wght,
                             const int*   __restrict__ src,
                             const int*   __restrict__ dst) {
    __shared__ int   ss[NEDGE], sd[NEDGE];
    __shared__ float sw[NEDGE];
    __shared__ short rlist[NEDGE], tmpl[NEDGE];
    __shared__ unsigned char accf[NEDGE];
    const int lane = threadIdx.x;
    const float K2 = 2.8853900817779268f;  // 2 * log2(e)

    for (int e = lane; e < NEDGE; e += 32) {
        ss[e] = src[e]; sd[e] = dst[e]; sw[e] = wght[e] * K2;
        rlist[e] = (short)e;
    }
    __syncwarp();

    const unsigned ltmask = (1u << lane) - 1u;
    uint2 dummy; dummy.x = (256u << 16) | 256u;  // scratch row 64
    dummy.y = __float_as_uint(0.0f);             // tanh(0)=0 -> no-op

    unsigned long long Wprev = 0ull;   // member writes of previous chunk
    int nrem = NEDGE, nch = 0;
    while (nrem > 0) {
        for (int i = lane; i < nrem; i += 32) accf[i] = 0;
        __syncwarp();

        unsigned long long Wall = 0ull, Rall = 0ull, Wmem = 0ull;
        int members = 0;
        for (int base = 0; base < nrem && members < G; base += 32) {
            const int  idx   = base + lane;
            const bool valid = idx < nrem;
            const int  e = valid ? rlist[idx] : 0;
            const int  s = ss[e], d = sd[e];
            const unsigned long long myW = valid ? (1ull << d) : 0ull;
            const unsigned long long myR = valid ? (1ull << s) : 0ull;
            const unsigned long long iW = orscan_incl(myW, lane);
            const unsigned long long iR = orscan_incl(myR, lane);
            unsigned lo = __shfl_up_sync(0xffffffffu, (unsigned)iW, 1);
            unsigned hi = __shfl_up_sync(0xffffffffu, (unsigned)(iW >> 32), 1);
            const unsigned long long eW =
                (lane == 0) ? 0ull : (((unsigned long long)hi << 32) | lo);
            lo = __shfl_up_sync(0xffffffffu, (unsigned)iR, 1);
            hi = __shfl_up_sync(0xffffffffu, (unsigned)(iR >> 32), 1);
            const unsigned long long eR =
                (lane == 0) ? 0ull : (((unsigned long long)hi << 32) | lo);

            const unsigned long long tWall = Wall | eW;  // excl scan, all W
            const unsigned long long tRall = Rall | eR;  // excl scan, all R
            const bool ok0 = valid &&
                             !((tWall >> s) & 1ull) &&
                             !((tRall >> d) & 1ull) &&
                             !((Wmem  >> d) & 1ull) &&
                             !((Wprev >> s) & 1ull) &&   // distance-2: src
                             !((Wprev >> d) & 1ull);     // distance-2: dst
            // intra-batch member-dst dedup (keep lowest ok0 lane per dst)
            const unsigned peers = __match_any_sync(0xffffffffu, d);
            const unsigned bal0  = __ballot_sync(0xffffffffu, ok0);
            const bool ok = ok0 && ((peers & bal0 & ltmask) == 0u);
            const unsigned bal  = __ballot_sync(0xffffffffu, ok);
            const int      rank = members + __popc(bal & ltmask);
            const bool accept = ok && (rank < G);
            if (accept) {
                uint2 rec;
                rec.x = ((unsigned)(d * 4) << 16) | (unsigned)(s * 4);
                rec.y = __float_as_uint(sw[e]);
                g_recs[nch * G + rank] = rec;
                accf[idx] = 1;
            }
            members += __popc(__ballot_sync(0xffffffffu, accept));
            Wall |= bcast64(iW, 31);
            Rall |= bcast64(iR, 31);
            const unsigned accWlo = __reduce_or_sync(0xffffffffu,
                accept ? (unsigned)(1ull << d) : 0u);
            const unsigned accWhi = __reduce_or_sync(0xffffffffu,
                accept ? (unsigned)((1ull << d) >> 32) : 0u);
            Wmem |= ((unsigned long long)accWhi << 32) | accWlo;
        }
        if (lane >= members && lane < G) g_recs[nch * G + lane] = dummy;
        Wprev = Wmem;   // (empty chunk -> 0 -> progress guaranteed)
        // compact remaining list (program order preserved)
        int wrpos = 0;
        for (int base = 0; base < nrem; base += 32) {
            const int  idx   = base + lane;
            const bool valid = idx < nrem;
            const int  e     = valid ? rlist[idx] : 0;
            const bool keep  = valid && !accf[idx];
            const unsigned kb = __ballot_sync(0xffffffffu, keep);
            if (keep) tmpl[wrpos + __popc(kb & ltmask)] = (short)e;
            wrpos += __popc(kb);
        }
        __syncwarp();
        for (int i = lane; i < wrpos; i += 32) rlist[i] = tmpl[i];
        __syncwarp();
        nrem = wrpos;
        nch++;
    }
    // trailing all-dummy chunk (pass-boundary distance-2 spacer)
    if (lane < G) g_recs[nch * G + lane] = dummy;
    nch++;
    // wrap entry = copy of chunk 0 (prefetch wrap-around)
    if (lane < G) g_recs[nch * G + lane] = g_recs[lane];
    if (lane == 0) g_nchunks = nch;
}

// ---------------------------------------------------------------------------
// Main kernel, software-pipelined: warp = 2 columns x 16 edge slots; node
// state [col][row] in smem, stride 65. Per iteration: load chunk c+1's src &
// dst values (legal before chunk c's stores via the distance-2 schedule),
// then compute+store chunk c, then __syncwarp. The 29-cyc LDS latency hides
// under the 2xMUFU chain. tanh(x) = 1 - 2/(exp2(x*2log2e)+1) via ex2/rcp.
// ---------------------------------------------------------------------------
__global__ void __launch_bounds__(TB, 1)
net_kernel(const float* __restrict__ x, float* __restrict__ out) {
    __shared__ float vals[CPB * STRIDE];

    const int tid  = threadIdx.x;
    const int lane = tid & 31;
    const int wid  = tid >> 5;
    const int cl   = wid * 2 + (lane >> 4);  // local column 0..7
    const int slot = lane & 15;
    const int bc   = blockIdx.x * CPB;

    for (int i = tid; i < CPB * NINPUT; i += TB) {
        const int r = i >> 3, c = i & 7;
        vals[c * STRIDE + r] = x[r * BATCH + bc + c];
    }
    for (int i = tid; i < CPB * (STRIDE - NINPUT); i += TB) {
        const int r = NINPUT + (i >> 3), c = i & 7;
        vals[c * STRIDE + r] = 0.0f;
    }
    __syncthreads();

    const int nch = g_nchunks;          // incl. trailing dummy chunk
    char* base = (char*)(vals + cl * STRIDE);

    // prime the pipeline with chunk 0
    uint2 rec = __ldg(&g_recs[slot]);
    float vsrc = *(const float*)(base + (rec.x & 0xffffu));
    float vdst = *(const float*)(base + (rec.x >> 16));

    #pragma unroll 1
    for (int p = 0; p < PASSES; p++) {
        #pragma unroll 2
        for (int c = 0; c < nch; c++) {
            const uint2 nxt = __ldg(&g_recs[(c + 1) * G + slot]); // wrap=chunk0
            // next-chunk loads BEFORE current stores (distance-2 guarantees
            // these addresses are not written by the current chunk)
            const float nsrc = *(const float*)(base + (nxt.x & 0xffffu));
            const float ndst = *(const float*)(base + (nxt.x >> 16));
            // compute + store current chunk
            const float a = vsrc * __uint_as_float(rec.y);
            float ev;  asm("ex2.approx.f32 %0, %1;" : "=f"(ev) : "f"(a));
            float r2;  asm("rcp.approx.f32 %0, %1;" : "=f"(r2) : "f"(ev + 1.0f));
            *(float*)(base + (rec.x >> 16)) = fmaf(-2.0f, r2, vdst + 1.0f);
            rec = nxt; vsrc = nsrc; vdst = ndst;
            __syncwarp();
        }
    }
    __syncthreads();

    for (int i = tid; i < CPB * NOUT; i += TB) {
        const int r = i >> 3, c = i & 7;
        out[r * BATCH + bc + c] = tanhf(vals[c * STRIDE + NINPUT + r]);
    }
}

extern "C" void kernel_launch(void* const* d_in, const int* in_sizes, int n_in,
                              void* d_out, int out_size) {
    const float* x   = (const float*)d_in[0];
    const float* w   = (const float*)d_in[1];
    const int*   src = (const int*)d_in[2];
    const int*   dst = (const int*)d_in[3];
    (void)in_sizes; (void)n_in; (void)out_size;

    sched_kernel<<<1, 32>>>(w, src, dst);
    net_kernel<<<GRIDB, TB>>>(x, (float*)d_out);
}

// round 12
// speedup vs baseline: 1.4107x; 1.4107x over previous
#include <cuda_runtime.h>
#include <cstdint>

#define NODES   64
#define NINPUT  16
#define NOUT    8
#define NEDGE   256
#define BATCH   8192
#define PASSES  64
#define G       16            // edge slots per chunk (lanes per column)
#define TB      128           // threads per block
#define CPB     8             // columns per block (2 cols per warp)
#define GRIDB   (BATCH / CPB) // 1024 blocks
#define STRIDE  65            // floats per column (64 nodes + scratch row 64)
#define MAXCH   257           // worst case chunks + wrap chunk

__device__ uint4 g_recs[MAXCH * G + G];   // {src_off, dst_off, w_bits, 0}
__device__ int   g_nchunks;

// 64-bit inclusive OR-scan across the warp
__device__ __forceinline__ unsigned long long orscan_incl(unsigned long long x,
                                                          int lane) {
    #pragma unroll
    for (int o = 1; o < 32; o <<= 1) {
        unsigned lo = __shfl_up_sync(0xffffffffu, (unsigned)x, o);
        unsigned hi = __shfl_up_sync(0xffffffffu, (unsigned)(x >> 32), o);
        unsigned long long y = ((unsigned long long)hi << 32) | lo;
        if (lane >= o) x |= y;
    }
    return x;
}

__device__ __forceinline__ unsigned long long bcast64(unsigned long long x,
                                                      int srclane) {
    unsigned lo = __shfl_sync(0xffffffffu, (unsigned)x, srclane);
    unsigned hi = __shfl_sync(0xffffffffu, (unsigned)(x >> 32), srclane);
    return ((unsigned long long)hi << 32) | lo;
}

// ---------------------------------------------------------------------------
// Warp-parallel greedy list scheduler (the verified R6 version, unchanged
// rules, uint4 output). Dependence rules for the sum-accumulation graph:
//   RAW: candidate src not written by any earlier remaining edge/member
//   WAR: candidate dst not read by any earlier remaining edge/member
//   in-chunk WAW race: member dsts pairwise distinct
//   WAW across chunks: unordered (fp adds commute; reassociation only)
// accf[] zero-filled for all remaining positions each chunk (R5 lesson).
// rec = {src_byte_off, dst_byte_off, w * 2*log2(e), 0}.
// ---------------------------------------------------------------------------
__global__ void sched_kernel(const float* __restrict__ wght,
                             const int*   __restrict__ src,
                             const int*   __restrict__ dst) {
    __shared__ int   ss[NEDGE], sd[NEDGE];
    __shared__ float sw[NEDGE];
    __shared__ short rlist[NEDGE], tmpl[NEDGE];
    __shared__ unsigned char accf[NEDGE];
    const int lane = threadIdx.x;
    const float K2 = 2.8853900817779268f;  // 2 * log2(e)

    for (int e = lane; e < NEDGE; e += 32) {
        ss[e] = src[e]; sd[e] = dst[e]; sw[e] = wght[e] * K2;
        rlist[e] = (short)e;
    }
    __syncwarp();

    const unsigned ltmask = (1u << lane) - 1u;
    uint4 dummy; dummy.x = 256u; dummy.y = 256u;   // scratch row 64
    dummy.z = 0u; dummy.w = 0u;                    // w=0 -> exact no-op

    int nrem = NEDGE, nch = 0;
    while (nrem > 0) {
        // clear accept flags for every remaining position (scan may early-exit)
        for (int i = lane; i < nrem; i += 32) accf[i] = 0;
        __syncwarp();

        unsigned long long Wall = 0ull, Rall = 0ull, Wmem = 0ull;
        int members = 0;
        for (int base = 0; base < nrem && members < G; base += 32) {
            const int  idx   = base + lane;
            const bool valid = idx < nrem;
            const int  e = valid ? rlist[idx] : 0;
            const int  s = ss[e], d = sd[e];
            const unsigned long long myW = valid ? (1ull << d) : 0ull;
            const unsigned long long myR = valid ? (1ull << s) : 0ull;
            const unsigned long long iW = orscan_incl(myW, lane);
            const unsigned long long iR = orscan_incl(myR, lane);
            unsigned lo = __shfl_up_sync(0xffffffffu, (unsigned)iW, 1);
            unsigned hi = __shfl_up_sync(0xffffffffu, (unsigned)(iW >> 32), 1);
            const unsigned long long eW =
                (lane == 0) ? 0ull : (((unsigned long long)hi << 32) | lo);
            lo = __shfl_up_sync(0xffffffffu, (unsigned)iR, 1);
            hi = __shfl_up_sync(0xffffffffu, (unsigned)(iR >> 32), 1);
            const unsigned long long eR =
                (lane == 0) ? 0ull : (((unsigned long long)hi << 32) | lo);

            const unsigned long long tWall = Wall | eW;  // excl scan, all W
            const unsigned long long tRall = Rall | eR;  // excl scan, all R
            const bool ok0 = valid &&
                             !((tWall >> s) & 1ull) &&
                             !((tRall >> d) & 1ull) &&
                             !((Wmem  >> d) & 1ull);
            // intra-batch member-dst dedup (keep lowest ok0 lane per dst)
            const unsigned peers = __match_any_sync(0xffffffffu, d);
            const unsigned bal0  = __ballot_sync(0xffffffffu, ok0);
            const bool ok = ok0 && ((peers & bal0 & ltmask) == 0u);
            const unsigned bal  = __ballot_sync(0xffffffffu, ok);
            const int      rank = members + __popc(bal & ltmask);
            const bool accept = ok && (rank < G);
            if (accept) {
                uint4 rec;
                rec.x = (unsigned)(s * 4);
                rec.y = (unsigned)(d * 4);
                rec.z = __float_as_uint(sw[e]);
                rec.w = 0u;
                g_recs[nch * G + rank] = rec;
                accf[idx] = 1;
            }
            members += __popc(__ballot_sync(0xffffffffu, accept));
            // fold footprints of everything scanned + member write set
            Wall |= bcast64(iW, 31);
            Rall |= bcast64(iR, 31);
            const unsigned accWlo = __reduce_or_sync(0xffffffffu,
                accept ? (unsigned)(1ull << d) : 0u);
            const unsigned accWhi = __reduce_or_sync(0xffffffffu,
                accept ? (unsigned)((1ull << d) >> 32) : 0u);
            Wmem |= ((unsigned long long)accWhi << 32) | accWlo;
        }
        if (lane >= members && lane < G) g_recs[nch * G + lane] = dummy;
        // compact remaining list (program order preserved)
        int wrpos = 0;
        for (int base = 0; base < nrem; base += 32) {
            const int  idx   = base + lane;
            const bool valid = idx < nrem;
            const int  e     = valid ? rlist[idx] : 0;
            const bool keep  = valid && !accf[idx];
            const unsigned kb = __ballot_sync(0xffffffffu, keep);
            if (keep) tmpl[wrpos + __popc(kb & ltmask)] = (short)e;
            wrpos += __popc(kb);
        }
        __syncwarp();
        for (int i = lane; i < wrpos; i += 32) rlist[i] = tmpl[i];
        __syncwarp();
        nrem = wrpos;
        nch++;
    }
    // wrap chunk = copy of chunk 0 (prefetch wrap-around)
    if (lane < G) g_recs[nch * G + lane] = g_recs[lane];
    if (lane == 0) g_nchunks = nch;
}

// ---------------------------------------------------------------------------
// Main kernel: warp = 2 columns x 16 edge slots; node state [col][row] in
// smem, stride 65. NO per-chunk __syncwarp: the warp is converged (uniform
// branches only), all 32 lanes issue each instruction together, and the smem
// pipe processes a warp's accesses in program order -- so chunk c's STS is
// globally ordered before chunk c+1's LDS. A compiler memory barrier per
// iteration pins program order (smem offsets are dynamic, so ptxas must
// preserve it anyway). tanh(x) = 1 - 2/(exp2(x*2log2e)+1) via MUFU ex2/rcp.
// ---------------------------------------------------------------------------
__global__ void __launch_bounds__(TB, 1)
net_kernel(const float* __restrict__ x, float* __restrict__ out) {
    __shared__ float vals[CPB * STRIDE];

    const int tid  = threadIdx.x;
    const int lane = tid & 31;
    const int wid  = tid >> 5;
    const int cl   = wid * 2 + (lane >> 4);  // local column 0..7
    const int slot = lane & 15;
    const int bc   = blockIdx.x * CPB;

    for (int i = tid; i < CPB * NINPUT; i += TB) {
        const int r = i >> 3, c = i & 7;
        vals[c * STRIDE + r] = x[r * BATCH + bc + c];
    }
    for (int i = tid; i < CPB * (STRIDE - NINPUT); i += TB) {
        const int r = NINPUT + (i >> 3), c = i & 7;
        vals[c * STRIDE + r] = 0.0f;
    }
    __syncthreads();

    const int nch = g_nchunks;
    char* base = (char*)(vals + cl * STRIDE);

    uint4 rec = __ldg(&g_recs[slot]);
    #pragma unroll 1
    for (int p = 0; p < PASSES; p++) {
        #pragma unroll 2
        for (int c = 0; c < nch; c++) {
            const uint4 nxt = __ldg(&g_recs[(c + 1) * G + slot]);  // wrap=chunk0
            const float v  = *(const float*)(base + rec.x);        // src
            const float t1 = *(const float*)(base + rec.y) + 1.0f; // dst + 1
            const float a = v * __uint_as_float(rec.z);
            float ev;  asm("ex2.approx.f32 %0, %1;" : "=f"(ev) : "f"(a));
            float r2;  asm("rcp.approx.f32 %0, %1;" : "=f"(r2) : "f"(ev + 1.0f));
            *(float*)(base + rec.y) = fmaf(-2.0f, r2, t1);  // pv + 1 - 2/(ev+1)
            rec = nxt;
            asm volatile("" ::: "memory");  // pin smem program order
        }
    }
    __syncthreads();

    for (int i = tid; i < CPB * NOUT; i += TB) {
        const int r = i >> 3, c = i & 7;
        out[r * BATCH + bc + c] = tanhf(vals[c * STRIDE + NINPUT + r]);
    }
}

extern "C" void kernel_launch(void* const* d_in, const int* in_sizes, int n_in,
                              void* d_out, int out_size) {
    const float* x   = (const float*)d_in[0];
    const float* w   = (const float*)d_in[1];
    const int*   src = (const int*)d_in[2];
    const int*   dst = (const int*)d_in[3];
    (void)in_sizes; (void)n_in; (void)out_size;

    sched_kernel<<<1, 32>>>(w, src, dst);
    net_kernel<<<GRIDB, TB>>>(x, (float*)d_out);
}

// round 14
// speedup vs baseline: 1.6405x; 1.1630x over previous
#include <cuda_runtime.h>
#include <cstdint>

#define NODES   64
#define NINPUT  16
#define NOUT    8
#define NEDGE   256
#define BATCH   8192
#define PASSES  64
#define G       16            // edge slots per chunk
#define TB      128           // threads per block (4 warps)
#define CPB     16            // columns per block (4 cols per warp via float2)
#define PAIRS   8             // column pairs per block
#define GRIDB   (BATCH / CPB) // 512 blocks
#define RS      65            // float2 rows per pair (64 nodes + scratch 64)
#define MAXCH   257           // worst case chunks + wrap chunk

__device__ uint2 g_recs[MAXCH * G + G];
__device__ int   g_nchunks;

// 64-bit inclusive OR-scan across the warp
__device__ __forceinline__ unsigned long long orscan_incl(unsigned long long x,
                                                          int lane) {
    #pragma unroll
    for (int o = 1; o < 32; o <<= 1) {
        unsigned lo = __shfl_up_sync(0xffffffffu, (unsigned)x, o);
        unsigned hi = __shfl_up_sync(0xffffffffu, (unsigned)(x >> 32), o);
        unsigned long long y = ((unsigned long long)hi << 32) | lo;
        if (lane >= o) x |= y;
    }
    return x;
}

__device__ __forceinline__ unsigned long long bcast64(unsigned long long x,
                                                      int srclane) {
    unsigned lo = __shfl_sync(0xffffffffu, (unsigned)x, srclane);
    unsigned hi = __shfl_sync(0xffffffffu, (unsigned)(x >> 32), srclane);
    return ((unsigned long long)hi << 32) | lo;
}

// ---------------------------------------------------------------------------
// Warp-parallel greedy list scheduler (verified R6 version). Dependence rules
// for the sum-accumulation graph:
//   RAW: candidate src not written by any earlier remaining edge/member
//   WAR: candidate dst not read by any earlier remaining edge/member
//   in-chunk WAW race: member dsts pairwise distinct
//   WAW across chunks: unordered (fp adds commute; reassociation only)
// accf[] zero-filled for all remaining positions each chunk (R5 lesson).
// rec.x = (dst_byte_off << 16) | src_byte_off with row stride 8 bytes
// (float2 node rows); rec.y = w * 2*log2(e).
// ---------------------------------------------------------------------------
__global__ void sched_kernel(const float* __restrict__ wght,
                             const int*   __restrict__ src,
                             const int*   __restrict__ dst) {
    __shared__ int   ss[NEDGE], sd[NEDGE];
    __shared__ float sw[NEDGE];
    __shared__ short rlist[NEDGE], tmpl[NEDGE];
    __shared__ unsigned char accf[NEDGE];
    const int lane = threadIdx.x;
    const float K2 = 2.8853900817779268f;  // 2 * log2(e)

    for (int e = lane; e < NEDGE; e += 32) {
        ss[e] = src[e]; sd[e] = dst[e]; sw[e] = wght[e] * K2;
        rlist[e] = (short)e;
    }
    __syncwarp();

    const unsigned ltmask = (1u << lane) - 1u;
    uint2 dummy; dummy.x = (512u << 16) | 512u;  // scratch row 64 (64*8)
    dummy.y = __float_as_uint(0.0f);             // tanh(0)=0 -> exact no-op

    int nrem = NEDGE, nch = 0;
    while (nrem > 0) {
        // clear accept flags for every remaining position (scan may early-exit)
        for (int i = lane; i < nrem; i += 32) accf[i] = 0;
        __syncwarp();

        unsigned long long Wall = 0ull, Rall = 0ull, Wmem = 0ull;
        int members = 0;
        for (int base = 0; base < nrem && members < G; base += 32) {
            const int  idx   = base + lane;
            const bool valid = idx < nrem;
            const int  e = valid ? rlist[idx] : 0;
            const int  s = ss[e], d = sd[e];
            const unsigned long long myW = valid ? (1ull << d) : 0ull;
            const unsigned long long myR = valid ? (1ull << s) : 0ull;
            const unsigned long long iW = orscan_incl(myW, lane);
            const unsigned long long iR = orscan_incl(myR, lane);
            unsigned lo = __shfl_up_sync(0xffffffffu, (unsigned)iW, 1);
            unsigned hi = __shfl_up_sync(0xffffffffu, (unsigned)(iW >> 32), 1);
            const unsigned long long eW =
                (lane == 0) ? 0ull : (((unsigned long long)hi << 32) | lo);
            lo = __shfl_up_sync(0xffffffffu, (unsigned)iR, 1);
            hi = __shfl_up_sync(0xffffffffu, (unsigned)(iR >> 32), 1);
            const unsigned long long eR =
                (lane == 0) ? 0ull : (((unsigned long long)hi << 32) | lo);

            const unsigned long long tWall = Wall | eW;  // excl scan, all W
            const unsigned long long tRall = Rall | eR;  // excl scan, all R
            const bool ok0 = valid &&
                             !((tWall >> s) & 1ull) &&
                             !((tRall >> d) & 1ull) &&
                             !((Wmem  >> d) & 1ull);
            // intra-batch member-dst dedup (keep lowest ok0 lane per dst)
            const unsigned peers = __match_any_sync(0xffffffffu, d);
            const unsigned bal0  = __ballot_sync(0xffffffffu, ok0);
            const bool ok = ok0 && ((peers & bal0 & ltmask) == 0u);
            const unsigned bal  = __ballot_sync(0xffffffffu, ok);
            const int      rank = members + __popc(bal & ltmask);
            const bool accept = ok && (rank < G);
            if (accept) {
                uint2 rec;
                rec.x = ((unsigned)(d * 8) << 16) | (unsigned)(s * 8);
                rec.y = __float_as_uint(sw[e]);
                g_recs[nch * G + rank] = rec;
                accf[idx] = 1;
            }
            members += __popc(__ballot_sync(0xffffffffu, accept));
            // fold footprints of everything scanned + member write set
            Wall |= bcast64(iW, 31);
            Rall |= bcast64(iR, 31);
            const unsigned accWlo = __reduce_or_sync(0xffffffffu,
                accept ? (unsigned)(1ull << d) : 0u);
            const unsigned accWhi = __reduce_or_sync(0xffffffffu,
                accept ? (unsigned)((1ull << d) >> 32) : 0u);
            Wmem |= ((unsigned long long)accWhi << 32) | accWlo;
        }
        if (lane >= members && lane < G) g_recs[nch * G + lane] = dummy;
        // compact remaining list (program order preserved)
        int wrpos = 0;
        for (int base = 0; base < nrem; base += 32) {
            const int  idx   = base + lane;
            const bool valid = idx < nrem;
            const int  e     = valid ? rlist[idx] : 0;
            const bool keep  = valid && !accf[idx];
            const unsigned kb = __ballot_sync(0xffffffffu, keep);
            if (keep) tmpl[wrpos + __popc(kb & ltmask)] = (short)e;
            wrpos += __popc(kb);
        }
        __syncwarp();
        for (int i = lane; i < wrpos; i += 32) rlist[i] = tmpl[i];
        __syncwarp();
        nrem = wrpos;
        nch++;
    }
    // wrap chunk = copy of chunk 0 (prefetch wrap-around)
    if (lane < G) g_recs[nch * G + lane] = g_recs[lane];
    if (lane == 0) g_nchunks = nch;
}

// ---------------------------------------------------------------------------
// Main kernel: warp = 2 column-PAIRS x 16 edge slots; each lane handles one
// edge for TWO batch columns via float2 (LDS.64/STS.64). A full-warp 64-bit
// smem op moves 256B = 2 wavefronts -- the crossbar floor -- so per-column
// smem traffic drops ~3x vs scalar. Node state: vals[pair][row] as float2,
// row 64 = scratch for dummy slots. __syncwarp() orders smem between chunks.
// tanh(x) = 1 - 2/(exp2(x*2log2e)+1) via MUFU ex2/rcp (~1e-6 per-op error).
// ---------------------------------------------------------------------------
__global__ void __launch_bounds__(TB, 1)
net_kernel(const float* __restrict__ x, float* __restrict__ out) {
    __shared__ float2 vals[PAIRS * RS];

    const int tid  = threadIdx.x;
    const int lane = tid & 31;
    const int wid  = tid >> 5;
    const int pair = wid * 2 + (lane >> 4);  // local pair 0..7
    const int slot = lane & 15;
    const int bc   = blockIdx.x * CPB;

    float* vf = (float*)vals;
    // inputs rows 0..15
    for (int i = tid; i < CPB * NINPUT; i += TB) {
        const int r = i >> 4, c = i & 15;
        vf[(((c >> 1) * RS) + r) * 2 + (c & 1)] = x[r * BATCH + bc + c];
    }
    // zeros rows 16..64
    for (int i = tid; i < CPB * (RS - NINPUT); i += TB) {
        const int r = NINPUT + (i >> 4), c = i & 15;
        vf[(((c >> 1) * RS) + r) * 2 + (c & 1)] = 0.0f;
    }
    __syncthreads();

    const int nch = g_nchunks;
    char* base = (char*)(vals + pair * RS);

    uint2 rec = __ldg(&g_recs[slot]);
    #pragma unroll 1
    for (int p = 0; p < PASSES; p++) {
        #pragma unroll 2
        for (int c = 0; c < nch; c++) {
            const uint2 nxt = __ldg(&g_recs[(c + 1) * G + slot]);  // wrap=chunk0
            const unsigned sb = rec.x & 0xffffu;
            const unsigned db = rec.x >> 16;
            const float wv = __uint_as_float(rec.y);
            const float2 v  = *(const float2*)(base + sb);   // src, 2 cols
            const float2 pv = *(const float2*)(base + db);   // dst, 2 cols
            const float a0 = v.x * wv;
            const float a1 = v.y * wv;
            float e0, e1, r0, r1;
            asm("ex2.approx.f32 %0, %1;" : "=f"(e0) : "f"(a0));
            asm("ex2.approx.f32 %0, %1;" : "=f"(e1) : "f"(a1));
            asm("rcp.approx.f32 %0, %1;" : "=f"(r0) : "f"(e0 + 1.0f));
            asm("rcp.approx.f32 %0, %1;" : "=f"(r1) : "f"(e1 + 1.0f));
            float2 res;
            res.x = fmaf(-2.0f, r0, pv.x + 1.0f);  // pv + 1 - 2/(e+1)
            res.y = fmaf(-2.0f, r1, pv.y + 1.0f);
            *(float2*)(base + db) = res;
            rec = nxt;
            __syncwarp();
        }
    }
    __syncthreads();

    for (int i = tid; i < CPB * NOUT; i += TB) {
        const int r = i >> 4, c = i & 15;
        const float vv = vf[(((c >> 1) * RS) + NINPUT + r) * 2 + (c & 1)];
        out[r * BATCH + bc + c] = tanhf(vv);
    }
}

extern "C" void kernel_launch(void* const* d_in, const int* in_sizes, int n_in,
                              void* d_out, int out_size) {
    const float* x   = (const float*)d_in[0];
    const float* w   = (const float*)d_in[1];
    const int*   src = (const int*)d_in[2];
    const int*   dst = (const int*)d_in[3];
    (void)in_sizes; (void)n_in; (void)out_size;

    sched_kernel<<<1, 32>>>(w, src, dst);
    net_kernel<<<GRIDB, TB>>>(x, (float*)d_out);
}